// round 14
// baseline (speedup 1.0000x reference)
#include <cuda_runtime.h>

// Problem constants
#define BATCH 2
#define DD 160
#define HH 160
#define WW 160
#define PLANE (HH * WW)               // 25600
#define NVOX (BATCH * DD * HH * WW)   // 8,192,000
#define NCH 5
#define RAD 4
#define INV_WIN (1.0f / 729.0f)

// ---- Kernel 1 (fused W+H, float4 prefix-shuffle stencil) ----
#define HCH 20                         // h rows per warp-pair task
#define NCHH (HH / HCH)                // 8
#define NTASK (BATCH * DD * NCHH)      // 2560 warp-pair tasks
#define PAIRS_PER_BLK 4
#define NTH1 (PAIRS_PER_BLK * 64)      // 256 threads (8 warps)
#define GRID1 (NTASK / PAIRS_PER_BLK)  // 640 blocks

// ---- Kernel 2 (D + cc) ----
#define W4 (WW / 4)                    // 40 float4 per row
#define PLANE4 (HH * W4)               // 6400
#define NVOX4 (NVOX / 4)
#define CDCHUNK 16
#define NCHUNK (DD / CDCHUNK)          // 10
#define HB 8                           // h rows per block
#define NTH2 (W4 * HB)                 // 320 threads
#define GRID2 (NCHUNK * BATCH * (HH / HB))  // 400 blocks

// Scratch (allocation-free: __device__ globals)
__device__ float g_buf[(size_t)NCH * NVOX];   // W+H summed, 5 channels
__device__ float g_partial[GRID2];

__device__ __forceinline__ float4 f4add(float4 a, const float4 v) {
    a.x += v.x; a.y += v.y; a.z += v.z; a.w += v.w; return a;
}
__device__ __forceinline__ float4 f4sub(float4 a, const float4 v) {
    a.x -= v.x; a.y -= v.y; a.z -= v.z; a.w -= v.w; return a;
}

// ---------------------------------------------------------------------------
// Kernel 1: fused products + H-running-window (registers, float4 lanes) +
// 9-tap W-sum via warp prefix difference on 4-col-per-lane layout.
// Warp pair per row: side 0 spans cols [0,127] (emits 0..123), side 1 spans
// [32,159] (emits 124..159). 13 shuffles per channel per 128 columns.
// ---------------------------------------------------------------------------
__global__ void __launch_bounds__(NTH1) pass_wh_kernel(const float* __restrict__ I,
                                                       const float* __restrict__ J) {
    const int tid = threadIdx.x;
    const int warpId = tid >> 5;
    const int lane = tid & 31;
    const int side = warpId & 1;                   // 0: cols 0..127, 1: 32..159

    const int pairIdx = blockIdx.x * PAIRS_PER_BLK + (warpId >> 1);
    const int plane = pairIdx / NCHH;              // b*DD + d
    const int hc = pairIdx % NCHH;
    const int h0 = hc * HCH;

    const int span0 = side * 32;                   // first col of span
    const int c4 = span0 / 4 + lane;               // float4 index of this lane
    const size_t pbase4 = (size_t)plane * (PLANE / 4);
    const float4* __restrict__ Ip = (const float4*)I + pbase4 + c4;
    const float4* __restrict__ Jp = (const float4*)J + pbase4 + c4;

    // emit predicate: side0 -> lanes 0..30 (cols 0..123); side1 -> lanes >=23 (cols 124..159)
    const bool emit = side ? (lane >= 23) : (lane <= 30);
    float4* __restrict__ obase = (float4*)g_buf + pbase4 + c4;

    // H running sums of the 5 product channels (float4 = 4 columns each)
    float4 S0 = {0,0,0,0}, S1 = {0,0,0,0}, S2 = {0,0,0,0}, S3 = {0,0,0,0}, S4 = {0,0,0,0};

    #pragma unroll
    for (int k = -RAD; k <= RAD; k++) {
        const int hh = h0 + k;
        if (hh >= 0) {
            const float4 iv = Ip[(size_t)hh * W4];
            const float4 jv = Jp[(size_t)hh * W4];
            S0 = f4add(S0, iv);
            S1 = f4add(S1, jv);
            S2.x += iv.x * iv.x; S2.y += iv.y * iv.y; S2.z += iv.z * iv.z; S2.w += iv.w * iv.w;
            S3.x += jv.x * jv.x; S3.y += jv.y * jv.y; S3.z += jv.z * jv.z; S3.w += jv.w * jv.w;
            S4.x += iv.x * jv.x; S4.y += iv.y * jv.y; S4.z += iv.z * jv.z; S4.w += iv.w * jv.w;
        }
    }

    for (int h = h0; h < h0 + HCH; h++) {
        // 9-tap W-sum per channel: out[m] = P[min(m+4,127)] - (m>=5 ? P[m-5] : 0)
        // with P = inclusive prefix over the warp's 128-col span.
        #define WSUM(dst, src)                                                   \
        {                                                                        \
            float4 p;                                                            \
            p.x = (src).x;                                                       \
            p.y = p.x + (src).y;                                                 \
            p.z = p.y + (src).z;                                                 \
            p.w = p.z + (src).w;                                                 \
            float t = p.w, u;                                                    \
            u = __shfl_up_sync(0xFFFFFFFFu, t, 1);  if (lane >= 1)  t += u;      \
            u = __shfl_up_sync(0xFFFFFFFFu, t, 2);  if (lane >= 2)  t += u;      \
            u = __shfl_up_sync(0xFFFFFFFFu, t, 4);  if (lane >= 4)  t += u;      \
            u = __shfl_up_sync(0xFFFFFFFFu, t, 8);  if (lane >= 8)  t += u;      \
            u = __shfl_up_sync(0xFFFFFFFFu, t, 16); if (lane >= 16) t += u;      \
            const float excl = t - p.w;                                          \
            p.x += excl; p.y += excl; p.z += excl; p.w += excl;                  \
            /* hi[e] = P[4(L+1)+e] from lane L+1; lane31: clamp -> own P.w */    \
            float4 hi;                                                           \
            hi.x = __shfl_down_sync(0xFFFFFFFFu, p.x, 1);                        \
            hi.y = __shfl_down_sync(0xFFFFFFFFu, p.y, 1);                        \
            hi.z = __shfl_down_sync(0xFFFFFFFFu, p.z, 1);                        \
            hi.w = __shfl_down_sync(0xFFFFFFFFu, p.w, 1);                        \
            if (lane == 31) { hi.x = p.w; hi.y = p.w; hi.z = p.w; hi.w = p.w; }  \
            /* lo: P[m-5]; e=0 -> lane L-2 elem3; e=1..3 -> lane L-1 elems 0..2 */\
            float4 lo;                                                           \
            lo.x = __shfl_up_sync(0xFFFFFFFFu, p.w, 2);                          \
            lo.y = __shfl_up_sync(0xFFFFFFFFu, p.x, 1);                          \
            lo.z = __shfl_up_sync(0xFFFFFFFFu, p.y, 1);                          \
            lo.w = __shfl_up_sync(0xFFFFFFFFu, p.z, 1);                          \
            if (lane < 2) lo.x = 0.f;                                            \
            if (lane < 1) { lo.y = 0.f; lo.z = 0.f; lo.w = 0.f; }                \
            dst.x = hi.x - lo.x;                                                 \
            dst.y = hi.y - lo.y;                                                 \
            dst.z = hi.z - lo.z;                                                 \
            dst.w = hi.w - lo.w;                                                 \
        }
        float4 o0, o1, o2, o3, o4;
        WSUM(o0, S0) WSUM(o1, S1) WSUM(o2, S2) WSUM(o3, S3) WSUM(o4, S4)
        #undef WSUM

        if (emit) {
            const size_t ob = (size_t)h * W4;
            obase[0 * (size_t)NVOX4 + ob] = o0;
            obase[1 * (size_t)NVOX4 + ob] = o1;
            obase[2 * (size_t)NVOX4 + ob] = o2;
            obase[3 * (size_t)NVOX4 + ob] = o3;
            obase[4 * (size_t)NVOX4 + ob] = o4;
        }

        // slide H window: add row h+5, subtract row h-4
        if (h != h0 + HCH - 1) {
            const int ha = h + 1 + RAD;
            if (ha < HH) {
                const float4 iv = Ip[(size_t)ha * W4];
                const float4 jv = Jp[(size_t)ha * W4];
                S0 = f4add(S0, iv);
                S1 = f4add(S1, jv);
                S2.x += iv.x * iv.x; S2.y += iv.y * iv.y; S2.z += iv.z * iv.z; S2.w += iv.w * iv.w;
                S3.x += jv.x * jv.x; S3.y += jv.y * jv.y; S3.z += jv.z * jv.z; S3.w += jv.w * jv.w;
                S4.x += iv.x * jv.x; S4.y += iv.y * jv.y; S4.z += iv.z * jv.z; S4.w += iv.w * jv.w;
            }
            const int hs = h - RAD;
            if (hs >= 0) {
                const float4 iv = Ip[(size_t)hs * W4];
                const float4 jv = Jp[(size_t)hs * W4];
                S0 = f4sub(S0, iv);
                S1 = f4sub(S1, jv);
                S2.x -= iv.x * iv.x; S2.y -= iv.y * iv.y; S2.z -= iv.z * iv.z; S2.w -= iv.w * iv.w;
                S3.x -= jv.x * jv.x; S3.y -= jv.y * jv.y; S3.z -= jv.z * jv.z; S3.w -= jv.w * jv.w;
                S4.x -= iv.x * jv.x; S4.y -= iv.y * jv.y; S4.z -= iv.z * jv.z; S4.w -= iv.w * jv.w;
            }
        }
    }
}

// ---------------------------------------------------------------------------
// Kernel 2: sliding-sum along D (float4) + fused NCC + block reduction.
// Interior chunks take a branch-free unrolled fast path.
// ---------------------------------------------------------------------------
__global__ void __launch_bounds__(NTH2) pass_d_kernel() {
    const int tid = threadIdx.x;
    const int w4 = tid % W4;
    const int hs = tid / W4;           // 0..HB-1
    const int bx = blockIdx.x;
    const int chunk = bx / (BATCH * (HH / HB));
    const int rem = bx % (BATCH * (HH / HB));
    const int b = rem / (HH / HB);
    const int ht = rem % (HH / HB);
    const int h = ht * HB + hs;
    const int d0 = chunk * CDCHUNK;

    const float4* __restrict__ in = (const float4*)g_buf;
    const size_t base = (size_t)b * DD * PLANE4 + (size_t)h * W4 + w4;

    float4 s[NCH];
    #pragma unroll
    for (int c = 0; c < NCH; c++) {
        float4 a = make_float4(0.f, 0.f, 0.f, 0.f);
        #pragma unroll
        for (int dd = d0 - RAD; dd <= d0 + RAD; dd++) {
            if (dd >= 0)   // upper bound d0+4 <= 148 < DD always
                a = f4add(a, in[(size_t)c * NVOX4 + base + (size_t)dd * PLANE4]);
        }
        s[c] = a;
    }

    float4 cc4 = make_float4(0.f, 0.f, 0.f, 0.f);

    #define CC_STEP()                                                         \
    {                                                                         \
        _Pragma("unroll")                                                     \
        for (int L = 0; L < 4; L++) {                                         \
            const float Is = (&s[0].x)[L], Js = (&s[1].x)[L],                 \
                        I2 = (&s[2].x)[L], J2 = (&s[3].x)[L],                 \
                        IJ = (&s[4].x)[L];                                    \
            const float cross = IJ - Is * Js * INV_WIN;                       \
            const float Iv = I2 - Is * Is * INV_WIN;                          \
            const float Jv = J2 - Js * Js * INV_WIN;                          \
            (&cc4.x)[L] += (cross * cross) / (Iv * Jv + 1e-5f);               \
        }                                                                     \
    }

    const bool fast = (d0 != 0) && (d0 != DD - CDCHUNK);
    if (fast) {
        #pragma unroll 4
        for (int d = d0; d < d0 + CDCHUNK - 1; d++) {
            CC_STEP();
            const int add = d + 1 + RAD;
            const int sub = d - RAD;
            #pragma unroll
            for (int c = 0; c < NCH; c++) {
                s[c] = f4add(s[c], in[(size_t)c * NVOX4 + base + (size_t)add * PLANE4]);
                s[c] = f4sub(s[c], in[(size_t)c * NVOX4 + base + (size_t)sub * PLANE4]);
            }
        }
        CC_STEP();
    } else {
        for (int d = d0; d < d0 + CDCHUNK - 1; d++) {
            CC_STEP();
            const int add = d + 1 + RAD;
            const int sub = d - RAD;
            #pragma unroll
            for (int c = 0; c < NCH; c++) {
                if (add < DD)
                    s[c] = f4add(s[c], in[(size_t)c * NVOX4 + base + (size_t)add * PLANE4]);
                if (sub >= 0)
                    s[c] = f4sub(s[c], in[(size_t)c * NVOX4 + base + (size_t)sub * PLANE4]);
            }
        }
        CC_STEP();
    }
    #undef CC_STEP

    float cc_sum = ((cc4.x + cc4.y) + (cc4.z + cc4.w));

    #pragma unroll
    for (int off = 16; off > 0; off >>= 1)
        cc_sum += __shfl_down_sync(0xFFFFFFFFu, cc_sum, off);

    __shared__ float warp_sums[NTH2 / 32];
    const int lane = tid & 31, warp = tid >> 5;
    if (lane == 0) warp_sums[warp] = cc_sum;
    __syncthreads();
    if (tid == 0) {
        float t = 0.f;
        #pragma unroll
        for (int i = 0; i < NTH2 / 32; i++) t += warp_sums[i];
        g_partial[blockIdx.x] = t;
    }
}

// ---------------------------------------------------------------------------
// Final deterministic reduction of block partials -> scalar out
// ---------------------------------------------------------------------------
__global__ void finalize_kernel(float* __restrict__ out) {
    __shared__ float red[256];
    float a = 0.f;
    for (int i = threadIdx.x; i < GRID2; i += 256) a += g_partial[i];
    red[threadIdx.x] = a;
    __syncthreads();
    #pragma unroll
    for (int off = 128; off > 0; off >>= 1) {
        if (threadIdx.x < off) red[threadIdx.x] += red[threadIdx.x + off];
        __syncthreads();
    }
    if (threadIdx.x == 0) out[0] = -red[0] / (float)NVOX;
}

// ---------------------------------------------------------------------------
extern "C" void kernel_launch(void* const* d_in, const int* in_sizes, int n_in,
                              void* d_out, int out_size) {
    const float* y_true = (const float*)d_in[0];
    const float* y_pred = (const float*)d_in[1];
    float* out = (float*)d_out;

    pass_wh_kernel<<<GRID1, NTH1>>>(y_true, y_pred);
    pass_d_kernel<<<GRID2, NTH2>>>();
    finalize_kernel<<<1, 256>>>(out);
}

// round 17
// speedup vs baseline: 1.2724x; 1.2724x over previous
#include <cuda_runtime.h>
#include <cuda_fp16.h>

// Problem constants
#define BATCH 2
#define DD 160
#define HH 160
#define WW 160
#define PLANE (HH * WW)               // 25600
#define NVOX (BATCH * DD * HH * WW)   // 8,192,000
#define NCH 5
#define RAD 4
#define INV_WIN (1.0f / 729.0f)

// ---- Kernel 1 (fused W+H, prefix-shuffle stencil, zero smem) ----
#define TEAMW 7                        // warps per row: 7*24 = 168 >= 160 outputs
#define NTH1 (TEAMW * 32)              // 224 threads
#define HCH 20                         // h rows per block
#define NCHH (HH / HCH)                // 8
#define GRID1 (BATCH * DD * NCHH)      // 2560 blocks

// ---- Kernel 2 (D + cc), 8 half-columns per thread ----
#define W8 (WW / 8)                    // 20 groups of 8 cols
#define CDCHUNK 16
#define NCHUNK (DD / CDCHUNK)          // 10
#define HB 8                           // h rows per block
#define NTH2 (W8 * HB)                 // 160 threads
#define HT2 (HH / HB)                  // 20
#define GRID2 (NCHUNK * BATCH * HT2)   // 400 blocks

// Scratch (allocation-free: __device__ globals)
__device__ __align__(16) __half g_buf[(size_t)NCH * NVOX];   // 82 MB
__device__ float g_partial[GRID2];
__device__ unsigned g_cnt = 0;         // self-resetting via atomicInc wrap

// ---------------------------------------------------------------------------
// Kernel 1: fused products + H-running-window (registers) + W-sum via warp
// prefix-sum difference (7 shuffles per channel). Stores fp16.
// ---------------------------------------------------------------------------
__global__ void __launch_bounds__(NTH1) pass_wh_kernel(const float* __restrict__ I,
                                                       const float* __restrict__ J) {
    const int tid = threadIdx.x;
    const int warp = tid >> 5;
    const int lane = tid & 31;

    const int bx = blockIdx.x;
    const int plane = bx / NCHH;       // b*DD + d
    const int hc = bx % NCHH;
    const int h0 = hc * HCH;

    const int w = warp * 24 + lane - 4;            // load column (may be OOB)
    const bool wvalid = (w >= 0 && w < WW);
    const int wc = min(max(w, 0), WW - 1);         // safe address
    const size_t pbase = (size_t)plane * PLANE;
    const float* __restrict__ Ip = I + pbase + wc;
    const float* __restrict__ Jp = J + pbase + wc;

    const bool emit = (lane >= 4) && (lane < 28) && (w < WW);

    // H running sums of the 5 products
    float S0 = 0.f, S1 = 0.f, S2 = 0.f, S3 = 0.f, S4 = 0.f;

    #pragma unroll
    for (int k = -RAD; k <= RAD; k++) {
        const int hh = h0 + k;
        if (hh >= 0) {
            const float iv = wvalid ? Ip[(size_t)hh * WW] : 0.f;
            const float jv = wvalid ? Jp[(size_t)hh * WW] : 0.f;
            S0 += iv; S1 += jv; S2 += iv * iv; S3 += jv * jv; S4 += iv * jv;
        }
    }

    for (int h = h0; h < h0 + HCH; h++) {
        // 9-tap W-sum via inclusive prefix + difference (7 shuffles):
        // out[lane] = P[lane+4] - P[lane-5]
        #define WSUM(dst, src)                                                \
        {                                                                     \
            float p = (src);                                                  \
            float t;                                                          \
            t = __shfl_up_sync(0xFFFFFFFFu, p, 1);  if (lane >= 1)  p += t;   \
            t = __shfl_up_sync(0xFFFFFFFFu, p, 2);  if (lane >= 2)  p += t;   \
            t = __shfl_up_sync(0xFFFFFFFFu, p, 4);  if (lane >= 4)  p += t;   \
            t = __shfl_up_sync(0xFFFFFFFFu, p, 8);  if (lane >= 8)  p += t;   \
            t = __shfl_up_sync(0xFFFFFFFFu, p, 16); if (lane >= 16) p += t;   \
            const float hi = __shfl_down_sync(0xFFFFFFFFu, p, 4);             \
            const float lo = __shfl_up_sync(0xFFFFFFFFu, p, 5);               \
            dst = hi - ((lane >= 5) ? lo : 0.f);                              \
        }
        float o0, o1, o2, o3, o4;
        WSUM(o0, S0) WSUM(o1, S1) WSUM(o2, S2) WSUM(o3, S3) WSUM(o4, S4)
        #undef WSUM

        if (emit) {
            const size_t obase = pbase + (size_t)h * WW + w;
            g_buf[0 * (size_t)NVOX + obase] = __float2half(o0);
            g_buf[1 * (size_t)NVOX + obase] = __float2half(o1);
            g_buf[2 * (size_t)NVOX + obase] = __float2half(o2);
            g_buf[3 * (size_t)NVOX + obase] = __float2half(o3);
            g_buf[4 * (size_t)NVOX + obase] = __float2half(o4);
        }

        // slide H window: add row h+5, subtract row h-4
        if (h != h0 + HCH - 1) {
            const int ha = h + 1 + RAD;
            if (ha < HH) {
                const float iv = wvalid ? Ip[(size_t)ha * WW] : 0.f;
                const float jv = wvalid ? Jp[(size_t)ha * WW] : 0.f;
                S0 += iv; S1 += jv; S2 += iv * iv; S3 += jv * jv; S4 += iv * jv;
            }
            const int hs = h - RAD;
            if (hs >= 0) {
                const float iv = wvalid ? Ip[(size_t)hs * WW] : 0.f;
                const float jv = wvalid ? Jp[(size_t)hs * WW] : 0.f;
                S0 -= iv; S1 -= jv; S2 -= iv * iv; S3 -= jv * jv; S4 -= iv * jv;
            }
        }
    }
}

// ---------------------------------------------------------------------------
// Kernel 2: sliding-sum along D on fp16 data (uint4 = 8 halves per load),
// fp32 running sums, fused NCC + deterministic global reduction (last block).
// ---------------------------------------------------------------------------
struct F8 { float v[8]; };

__device__ __forceinline__ F8 ld8(const __half* __restrict__ p) {
    const uint4 raw = *reinterpret_cast<const uint4*>(p);
    F8 r;
    const __half2* h = reinterpret_cast<const __half2*>(&raw);
    #pragma unroll
    for (int i = 0; i < 4; i++) {
        const float2 f = __half22float2(h[i]);
        r.v[2 * i] = f.x;
        r.v[2 * i + 1] = f.y;
    }
    return r;
}

__global__ void __launch_bounds__(NTH2) pass_d_kernel(float* __restrict__ out) {
    const int tid = threadIdx.x;
    const int w8 = tid % W8;
    const int hs = tid / W8;           // 0..HB-1
    const int bx = blockIdx.x;
    const int chunk = bx / (BATCH * HT2);
    const int rem = bx % (BATCH * HT2);
    const int b = rem / HT2;
    const int ht = rem % HT2;
    const int h = ht * HB + hs;
    const int d0 = chunk * CDCHUNK;

    const __half* __restrict__ in = g_buf;
    const size_t base = (size_t)b * DD * PLANE + (size_t)h * WW + w8 * 8;

    float s[NCH][8];
    #pragma unroll
    for (int c = 0; c < NCH; c++)
        #pragma unroll
        for (int k = 0; k < 8; k++) s[c][k] = 0.f;

    #pragma unroll
    for (int dd = d0 - RAD; dd <= d0 + RAD; dd++) {
        if (dd >= 0) {                 // dd <= d0+4 <= 148 < DD always
            #pragma unroll
            for (int c = 0; c < NCH; c++) {
                const F8 v = ld8(in + (size_t)c * NVOX + base + (size_t)dd * PLANE);
                #pragma unroll
                for (int k = 0; k < 8; k++) s[c][k] += v.v[k];
            }
        }
    }

    float cc[8];
    #pragma unroll
    for (int k = 0; k < 8; k++) cc[k] = 0.f;

    #define CC_STEP()                                                         \
    {                                                                         \
        _Pragma("unroll")                                                     \
        for (int k = 0; k < 8; k++) {                                         \
            const float Is = s[0][k], Js = s[1][k], I2 = s[2][k],             \
                        J2 = s[3][k], IJ = s[4][k];                           \
            const float cross = IJ - Is * Js * INV_WIN;                       \
            const float Iv = I2 - Is * Is * INV_WIN;                          \
            const float Jv = J2 - Js * Js * INV_WIN;                          \
            cc[k] += (cross * cross) / (Iv * Jv + 1e-5f);                     \
        }                                                                     \
    }

    const bool fast = (d0 != 0) && (d0 != DD - CDCHUNK);
    if (fast) {
        #pragma unroll 2
        for (int d = d0; d < d0 + CDCHUNK - 1; d++) {
            CC_STEP();
            const int add = d + 1 + RAD;
            const int sub = d - RAD;
            #pragma unroll
            for (int c = 0; c < NCH; c++) {
                const F8 va = ld8(in + (size_t)c * NVOX + base + (size_t)add * PLANE);
                const F8 vs = ld8(in + (size_t)c * NVOX + base + (size_t)sub * PLANE);
                #pragma unroll
                for (int k = 0; k < 8; k++) s[c][k] += va.v[k] - vs.v[k];
            }
        }
        CC_STEP();
    } else {
        for (int d = d0; d < d0 + CDCHUNK - 1; d++) {
            CC_STEP();
            const int add = d + 1 + RAD;
            const int sub = d - RAD;
            #pragma unroll
            for (int c = 0; c < NCH; c++) {
                if (add < DD) {
                    const F8 v = ld8(in + (size_t)c * NVOX + base + (size_t)add * PLANE);
                    #pragma unroll
                    for (int k = 0; k < 8; k++) s[c][k] += v.v[k];
                }
                if (sub >= 0) {
                    const F8 v = ld8(in + (size_t)c * NVOX + base + (size_t)sub * PLANE);
                    #pragma unroll
                    for (int k = 0; k < 8; k++) s[c][k] -= v.v[k];
                }
            }
        }
        CC_STEP();
    }
    #undef CC_STEP

    float cc_sum = ((cc[0] + cc[1]) + (cc[2] + cc[3])) +
                   ((cc[4] + cc[5]) + (cc[6] + cc[7]));

    // deterministic in-block reduction (warp shuffle, fixed order)
    const int lane = tid & 31, warp = tid >> 5;
    #pragma unroll
    for (int off = 16; off > 0; off >>= 1)
        cc_sum += __shfl_down_sync(0xFFFFFFFFu, cc_sum, off);

    __shared__ float warp_sums[NTH2 / 32];
    __shared__ bool s_last;
    if (lane == 0) warp_sums[warp] = cc_sum;
    __syncthreads();
    if (tid == 0) {
        float t = 0.f;
        #pragma unroll
        for (int i = 0; i < NTH2 / 32; i++) t += warp_sums[i];
        g_partial[blockIdx.x] = t;
        __threadfence();
        const unsigned old = atomicInc(&g_cnt, GRID2 - 1);   // wraps to 0: self-reset
        s_last = (old == GRID2 - 1);
    }
    __syncthreads();

    // Last block: final deterministic reduction.
    // NOTE: NTH2=160 is NOT a power of two -> no binary tree over threads.
    // Use strided accumulate + per-warp shuffle + serial 5-term sum (fixed order).
    if (s_last) {
        __threadfence();               // acquire: see all blocks' partials
        float a = 0.f;
        for (int i = tid; i < GRID2; i += NTH2) a += g_partial[i];
        #pragma unroll
        for (int off = 16; off > 0; off >>= 1)
            a += __shfl_down_sync(0xFFFFFFFFu, a, off);
        __shared__ float fin[NTH2 / 32];
        if (lane == 0) fin[warp] = a;
        __syncthreads();
        if (tid == 0) {
            float t = 0.f;
            #pragma unroll
            for (int i = 0; i < NTH2 / 32; i++) t += fin[i];
            out[0] = -t / (float)NVOX;
        }
    }
}

// ---------------------------------------------------------------------------
extern "C" void kernel_launch(void* const* d_in, const int* in_sizes, int n_in,
                              void* d_out, int out_size) {
    const float* y_true = (const float*)d_in[0];
    const float* y_pred = (const float*)d_in[1];
    float* out = (float*)d_out;

    pass_wh_kernel<<<GRID1, NTH1>>>(y_true, y_pred);
    pass_d_kernel<<<GRID2, NTH2>>>(out);
}